// round 2
// baseline (speedup 1.0000x reference)
#include <cuda_runtime.h>

#define N_TYPES 8
#define D 64
#define BM 128
#define E_MAX 1048576
typedef unsigned long long ull;

// ---------------- scratch ------------------------------------------------------
__device__ int g_counts[N_TYPES];
__device__ int g_cursor[N_TYPES];
__device__ int g_perm[E_MAX];
__device__ int g_is64;

// ---------------- helpers ------------------------------------------------------
__device__ __forceinline__ int get_type(const void* p, int i, int is64) {
    if (is64) return (int)((const long long*)p)[i];
    return ((const int*)p)[i];
}

__device__ __forceinline__ void ffma2(ull& c, ull a, ull b) {
    asm("fma.rn.f32x2 %0, %1, %2, %0;" : "+l"(c) : "l"(a), "l"(b));
}
__device__ __forceinline__ void unpack2(ull v, float& lo, float& hi) {
    unsigned a, b;
    asm("mov.b64 {%0, %1}, %2;" : "=r"(a), "=r"(b) : "l"(v));
    lo = __uint_as_float(a);
    hi = __uint_as_float(b);
}

// ---------------- launch 0: init + dtype detect --------------------------------
__global__ void k_init_detect(const int* __restrict__ t32, int E) {
    __shared__ int any;
    if (threadIdx.x == 0) any = 0;
    if (threadIdx.x < N_TYPES) {
        g_counts[threadIdx.x] = 0;
        g_cursor[threadIdx.x] = 0;
    }
    __syncthreads();
    int stride = E / 2048;
    if (stride < 1) stride = 1;
    for (int i = threadIdx.x; i < 1024; i += blockDim.x) {
        long long idx = 2LL * i * stride + 1;
        if (idx < E && t32[idx] != 0) any = 1;
    }
    __syncthreads();
    if (threadIdx.x == 0) g_is64 = any ? 0 : 1;
}

// ---------------- launch 1: histogram ------------------------------------------
__global__ void k_hist(const void* __restrict__ types, int E) {
    __shared__ int s[N_TYPES];
    if (threadIdx.x < N_TYPES) s[threadIdx.x] = 0;
    __syncthreads();
    int is64 = g_is64;
    for (int i = blockIdx.x * blockDim.x + threadIdx.x; i < E;
         i += gridDim.x * blockDim.x) {
        atomicAdd(&s[get_type(types, i, is64)], 1);
    }
    __syncthreads();
    if (threadIdx.x < N_TYPES) atomicAdd(&g_counts[threadIdx.x], s[threadIdx.x]);
}

// ---------------- launch 2: scatter (prefix computed locally) ------------------
__global__ void k_scatter(const void* __restrict__ types, int E) {
    __shared__ int s_cnt[N_TYPES], s_base[N_TYPES];
    if (threadIdx.x < N_TYPES) s_cnt[threadIdx.x] = 0;
    __syncthreads();
    int e = blockIdx.x * blockDim.x + threadIdx.x;
    int t = 0, local = 0;
    int valid = (e < E);
    if (valid) {
        t = get_type(types, e, g_is64);
        local = atomicAdd(&s_cnt[t], 1);
    }
    __syncthreads();
    if (threadIdx.x < N_TYPES) {
        // exclusive prefix of counts, computed redundantly per block (8 values)
        int off = 0;
        for (int u = 0; u < N_TYPES; u++) {
            if (u == threadIdx.x) break;
            off += g_counts[u];
        }
        s_base[threadIdx.x] = off + atomicAdd(&g_cursor[threadIdx.x], s_cnt[threadIdx.x]);
    }
    __syncthreads();
    if (valid) g_perm[s_base[t] + local] = e;
}

// ---------------- launch 3: grouped GEMM ---------------------------------------
// BM=128, N=64, K=64. X tile stored transposed AND duplicated so a-operands
// are directly loadable as aligned {x,x} 64-bit pairs (pure FFMA2 inner loop).
__global__ void __launch_bounds__(256, 2) k_gemm(const float* __restrict__ X,
                                                 const float* __restrict__ W,
                                                 const float* __restrict__ Bv,
                                                 float* __restrict__ out) {
    __shared__ float x_dup[D][2 * BM];  // 64KB: [k][2r]=x, [k][2r+1]=x
    __shared__ float w_s[D][D];         // 16KB: [k][col]

    // ---- map blockIdx.x -> (type, tile_in_type) via local prefix of counts ----
    int tile = blockIdx.x;
    int type = -1, row_start = 0, m = 0;
    {
        int acc_tiles = 0, off = 0;
#pragma unroll
        for (int t = 0; t < N_TYPES; t++) {
            int c = g_counts[t];
            int nt = (c + BM - 1) / BM;
            if (type < 0 && tile < acc_tiles + nt) {
                type = t;
                int lt = tile - acc_tiles;
                row_start = off + lt * BM;
                m = c - lt * BM;
                if (m > BM) m = BM;
            }
            acc_tiles += nt;
            off += c;
        }
    }
    if (type < 0) return;

    int tid = threadIdx.x;
    int rg = tid >> 3;  // 0..31 -> rows rg*4..rg*4+3
    int cg = tid & 7;   // 0..7  -> cols cg*8..cg*8+7

    // ---- accumulators pre-loaded with bias (as {b[c],b[c+1]} pairs) ----
    ull acc[4][4];
    {
        const ull* bb = reinterpret_cast<const ull*>(Bv + type * D + cg * 8);
        ull bi0 = bb[0], bi1 = bb[1], bi2 = bb[2], bi3 = bb[3];
#pragma unroll
        for (int i = 0; i < 4; i++) {
            acc[i][0] = bi0; acc[i][1] = bi1; acc[i][2] = bi2; acc[i][3] = bi3;
        }
    }

    // ---- load W[type] into smem ----
    {
        const float4* Wt = reinterpret_cast<const float4*>(W + type * D * D);
        float4* ws = reinterpret_cast<float4*>(&w_s[0][0]);
#pragma unroll
        for (int i = 0; i < D * D / 4 / 256; i++) ws[tid + i * 256] = Wt[tid + i * 256];
    }

    // ---- gather X rows -> transposed + duplicated smem ----
    {
        int row_idx = tid & (BM - 1);
        int half = tid >> 7;
        int rr = row_idx < m ? row_idx : (m - 1);
        int e = g_perm[row_start + rr];
        const float4* Xe = reinterpret_cast<const float4*>(X + (size_t)e * D) + half * 8;
#pragma unroll
        for (int q = 0; q < 8; q++) {
            float4 v = Xe[q];
            int k0 = (half * 8 + q) * 4;
            *reinterpret_cast<float2*>(&x_dup[k0 + 0][2 * row_idx]) = make_float2(v.x, v.x);
            *reinterpret_cast<float2*>(&x_dup[k0 + 1][2 * row_idx]) = make_float2(v.y, v.y);
            *reinterpret_cast<float2*>(&x_dup[k0 + 2][2 * row_idx]) = make_float2(v.z, v.z);
            *reinterpret_cast<float2*>(&x_dup[k0 + 3][2 * row_idx]) = make_float2(v.w, v.w);
        }
    }
    __syncthreads();

    // ---- main loop: 4x LDS.128 + 16x FFMA2 per k ----
#pragma unroll 16
    for (int k = 0; k < D; k++) {
        const ull* ap = reinterpret_cast<const ull*>(&x_dup[k][rg * 8]);
        ull a0 = ap[0], a1 = ap[1], a2 = ap[2], a3 = ap[3];
        const ull* bp = reinterpret_cast<const ull*>(&w_s[k][cg * 8]);
        ull b0 = bp[0], b1 = bp[1], b2 = bp[2], b3 = bp[3];
        ffma2(acc[0][0], a0, b0); ffma2(acc[0][1], a0, b1);
        ffma2(acc[0][2], a0, b2); ffma2(acc[0][3], a0, b3);
        ffma2(acc[1][0], a1, b0); ffma2(acc[1][1], a1, b1);
        ffma2(acc[1][2], a1, b2); ffma2(acc[1][3], a1, b3);
        ffma2(acc[2][0], a2, b0); ffma2(acc[2][1], a2, b1);
        ffma2(acc[2][2], a2, b2); ffma2(acc[2][3], a2, b3);
        ffma2(acc[3][0], a3, b0); ffma2(acc[3][1], a3, b1);
        ffma2(acc[3][2], a3, b2); ffma2(acc[3][3], a3, b3);
    }

    // ---- epilogue: relu + scattered store (bias already in acc) ----
#pragma unroll
    for (int i = 0; i < 4; i++) {
        int ridx = rg * 4 + i;
        if (ridx < m) {
            int e = g_perm[row_start + ridx];
            float v[8];
#pragma unroll
            for (int j = 0; j < 4; j++) unpack2(acc[i][j], v[2 * j], v[2 * j + 1]);
#pragma unroll
            for (int j = 0; j < 8; j++) v[j] = fmaxf(v[j], 0.0f);
            float4* op = reinterpret_cast<float4*>(out + (size_t)e * D + cg * 8);
            op[0] = make_float4(v[0], v[1], v[2], v[3]);
            op[1] = make_float4(v[4], v[5], v[6], v[7]);
        }
    }
}

// ---------------- launch -------------------------------------------------------
extern "C" void kernel_launch(void* const* d_in, const int* in_sizes, int n_in,
                              void* d_out, int out_size) {
    const float* X = (const float*)d_in[0];
    const void* types = d_in[1];  // int64 or int32, detected on device
    const float* W = (const float*)d_in[2];
    const float* Bv = (const float*)d_in[3];
    float* out = (float*)d_out;
    int E = in_sizes[0] / D;

    k_init_detect<<<1, 256>>>((const int*)types, E);
    k_hist<<<512, 256>>>(types, E);
    k_scatter<<<(E + 255) / 256, 256>>>(types, E);

    int max_tiles = (E + BM - 1) / BM + N_TYPES;
    k_gemm<<<max_tiles, 256>>>(X, W, Bv, out);
}

// round 5
// speedup vs baseline: 1.5865x; 1.5865x over previous
#include <cuda_runtime.h>
#include <cuda_bf16.h>
#include <cstdint>

#define N_TYPES 8
#define D 64
#define BM 128
#define E_MAX 1048576

// ---------------- scratch ------------------------------------------------------
__device__ int g_counts[N_TYPES];
__device__ int g_cursor[N_TYPES];
__device__ int g_perm[E_MAX];
__device__ int g_is64;

// ---------------- helpers ------------------------------------------------------
__device__ __forceinline__ int get_type(const void* p, int i, int is64) {
    if (is64) return (int)((const long long*)p)[i];
    return ((const int*)p)[i];
}

// pack two floats into bf16x2 word: low half = x0, high half = x1
__device__ __forceinline__ uint32_t bf16x2(float x0, float x1) {
    uint32_t r;
    asm("cvt.rn.bf16x2.f32 %0, %1, %2;" : "=r"(r) : "f"(x1), "f"(x0));
    return r;
}

// bf16 mma m16n8k16, fp32 accumulate
__device__ __forceinline__ void mma_bf16(float* c, const uint32_t* a,
                                         const uint32_t* b) {
    asm volatile(
        "mma.sync.aligned.m16n8k16.row.col.f32.bf16.bf16.f32 "
        "{%0,%1,%2,%3}, {%4,%5,%6,%7}, {%8,%9}, {%0,%1,%2,%3};"
        : "+f"(c[0]), "+f"(c[1]), "+f"(c[2]), "+f"(c[3])
        : "r"(a[0]), "r"(a[1]), "r"(a[2]), "r"(a[3]), "r"(b[0]), "r"(b[1]));
}

// ---------------- launch 0: init + dtype detect --------------------------------
__global__ void k_init_detect(const int* __restrict__ t32, int E) {
    __shared__ int any;
    if (threadIdx.x == 0) any = 0;
    if (threadIdx.x < N_TYPES) {
        g_counts[threadIdx.x] = 0;
        g_cursor[threadIdx.x] = 0;
    }
    __syncthreads();
    int stride = E / 2048;
    if (stride < 1) stride = 1;
    for (int i = threadIdx.x; i < 1024; i += blockDim.x) {
        long long idx = 2LL * i * stride + 1;
        if (idx < E && t32[idx] != 0) any = 1;
    }
    __syncthreads();
    if (threadIdx.x == 0) g_is64 = any ? 0 : 1;
}

// ---------------- launch 1: histogram ------------------------------------------
__global__ void k_hist(const void* __restrict__ types, int E) {
    __shared__ int s[N_TYPES];
    if (threadIdx.x < N_TYPES) s[threadIdx.x] = 0;
    __syncthreads();
    int is64 = g_is64;
    for (int i = blockIdx.x * blockDim.x + threadIdx.x; i < E;
         i += gridDim.x * blockDim.x) {
        atomicAdd(&s[get_type(types, i, is64)], 1);
    }
    __syncthreads();
    if (threadIdx.x < N_TYPES) atomicAdd(&g_counts[threadIdx.x], s[threadIdx.x]);
}

// ---------------- launch 2: scatter --------------------------------------------
__global__ void k_scatter(const void* __restrict__ types, int E) {
    __shared__ int s_cnt[N_TYPES], s_base[N_TYPES];
    if (threadIdx.x < N_TYPES) s_cnt[threadIdx.x] = 0;
    __syncthreads();
    int e = blockIdx.x * blockDim.x + threadIdx.x;
    int t = 0, local = 0;
    int valid = (e < E);
    if (valid) {
        t = get_type(types, e, g_is64);
        local = atomicAdd(&s_cnt[t], 1);
    }
    __syncthreads();
    if (threadIdx.x < N_TYPES) {
        int off = 0;
        for (int u = 0; u < N_TYPES; u++) {
            if (u == threadIdx.x) break;
            off += g_counts[u];
        }
        s_base[threadIdx.x] = off + atomicAdd(&g_cursor[threadIdx.x], s_cnt[threadIdx.x]);
    }
    __syncthreads();
    if (valid) g_perm[s_base[t] + local] = e;
}

// ---------------- launch 3: mma.sync bf16-split grouped GEMM -------------------
// Tile M=128, N=64, K=64. 8 warps in 4(m) x 2(n) grid; warp tile 32m x 32n.
// A/B stored in smem pre-swizzled to mma fragment layout (hi and lo bf16 planes).
// smem: A frags [h][ks4][mtile8][lane32] 16B = 32KB
//       B frags [h][ks4][ntile8][lane32]  8B = 16KB
//       W scratch fp32 [64][64]               = 16KB
static constexpr int SM_AF = 0;
static constexpr int SM_BF = 32768;
static constexpr int SM_WS = 49152;
static constexpr int SMEM_DYN = 65536;

__device__ __forceinline__ uint32_t afrag_off(int h, int ks, int mt, int lane) {
    return (uint32_t)((((h * 4 + ks) * 8 + mt) * 32 + lane) * 16);
}
__device__ __forceinline__ uint32_t bfrag_off(int h, int ks, int nt, int lane) {
    return (uint32_t)((((h * 4 + ks) * 8 + nt) * 32 + lane) * 8);
}

__global__ void __launch_bounds__(256) k_gemm_mma(const float* __restrict__ X,
                                                  const float* __restrict__ W,
                                                  const float* __restrict__ Bv,
                                                  float* __restrict__ out) {
    extern __shared__ char sm[];

    // ---- map blockIdx.x -> (type, tile) ----
    int tile = blockIdx.x;
    int type = -1, row_start = 0, m = 0;
    {
        int acc_tiles = 0, off = 0;
#pragma unroll
        for (int t = 0; t < N_TYPES; t++) {
            int c = g_counts[t];
            int nt = (c + BM - 1) / BM;
            if (type < 0 && tile < acc_tiles + nt) {
                type = t;
                int lt = tile - acc_tiles;
                row_start = off + lt * BM;
                m = c - lt * BM;
                if (m > BM) m = BM;
            }
            acc_tiles += nt;
            off += c;
        }
    }
    if (type < 0) return;

    int tid = threadIdx.x;

    // ================= phase 1: A fragment fill / W scratch load ===============
    if (tid < BM) {
        // one row per thread: gather, split bf16 hi/lo, scatter into frag layout
        int r = tid;
        int rr = (r < m) ? r : (m - 1);
        int e = g_perm[row_start + rr];
        int mt = r >> 4;
        int rt15 = r & 15;
        int lane_base = (rt15 & 7) * 4;
        int reg_rowadd = (rt15 >> 3);  // 0 or 1
        const float4* Xe = reinterpret_cast<const float4*>(X + (size_t)e * D);
#pragma unroll
        for (int q = 0; q < 16; q++) {
            float4 v = Xe[q];
#pragma unroll
            for (int pp = 0; pp < 2; pp++) {
                float x0 = pp ? v.z : v.x;
                float x1 = pp ? v.w : v.y;
                int p = q * 2 + pp;  // k-pair index 0..31
                uint32_t whi = bf16x2(x0, x1);
                float h0 = __uint_as_float(whi << 16);
                float h1 = __uint_as_float(whi & 0xffff0000u);
                uint32_t wlo = bf16x2(x0 - h0, x1 - h1);
                int ks = p >> 3;
                int pc = p & 7;
                int lane = lane_base + (pc & 3);
                int reg = reg_rowadd + ((pc >> 2) << 1);
                uint32_t ah = afrag_off(0, ks, mt, lane) + reg * 4;
                uint32_t al = afrag_off(1, ks, mt, lane) + reg * 4;
                *reinterpret_cast<uint32_t*>(sm + SM_AF + ah) = whi;
                *reinterpret_cast<uint32_t*>(sm + SM_AF + al) = wlo;
            }
        }
    } else {
        // load W[type] (16KB fp32) into scratch, linear
        int t = tid - BM;  // 0..127
        const float4* Wt = reinterpret_cast<const float4*>(W + (size_t)type * D * D);
        float4* ws = reinterpret_cast<float4*>(sm + SM_WS);
#pragma unroll
        for (int i = 0; i < 8; i++) ws[t + i * 128] = Wt[t + i * 128];
    }
    __syncthreads();

    // ================= phase 2: B fragment build from scratch ==================
    {
        const float* WS = reinterpret_cast<const float*>(sm + SM_WS);
#pragma unroll
        for (int j = 0; j < 4; j++) {
            int sid = tid * 4 + j;  // 0..1023 : [ks2][nt3][lane5]
            int ks = sid >> 8;
            int nt = (sid >> 5) & 7;
            int lane = sid & 31;
            int col = nt * 8 + (lane >> 2);
            int k0 = ks * 16 + 2 * (lane & 3);
            float w00 = WS[k0 * D + col];
            float w01 = WS[(k0 + 1) * D + col];
            float w10 = WS[(k0 + 8) * D + col];
            float w11 = WS[(k0 + 9) * D + col];
            uint32_t b0h = bf16x2(w00, w01);
            uint32_t b1h = bf16x2(w10, w11);
            float r00 = w00 - __uint_as_float(b0h << 16);
            float r01 = w01 - __uint_as_float(b0h & 0xffff0000u);
            float r10 = w10 - __uint_as_float(b1h << 16);
            float r11 = w11 - __uint_as_float(b1h & 0xffff0000u);
            uint32_t b0l = bf16x2(r00, r01);
            uint32_t b1l = bf16x2(r10, r11);
            *reinterpret_cast<uint2*>(sm + SM_BF + bfrag_off(0, ks, nt, lane)) =
                make_uint2(b0h, b1h);
            *reinterpret_cast<uint2*>(sm + SM_BF + bfrag_off(1, ks, nt, lane)) =
                make_uint2(b0l, b1l);
        }
    }
    __syncthreads();

    // ================= phase 3: mma main loop ==================================
    int wid = tid >> 5;
    int lane = tid & 31;
    int wm = (wid & 3) * 32;   // warp m offset
    int wn = (wid >> 2) * 32;  // warp n offset

    float acc[2][4][4];
#pragma unroll
    for (int mt = 0; mt < 2; mt++)
#pragma unroll
        for (int nt = 0; nt < 4; nt++)
#pragma unroll
            for (int i = 0; i < 4; i++) acc[mt][nt][i] = 0.0f;

#pragma unroll
    for (int ks = 0; ks < 4; ks++) {
        uint32_t a[2][2][4];  // [h][mt][reg]
#pragma unroll
        for (int mt = 0; mt < 2; mt++) {
            int gm = (wid & 3) * 2 + mt;
            *reinterpret_cast<uint4*>(a[0][mt]) =
                *reinterpret_cast<const uint4*>(sm + SM_AF + afrag_off(0, ks, gm, lane));
            *reinterpret_cast<uint4*>(a[1][mt]) =
                *reinterpret_cast<const uint4*>(sm + SM_AF + afrag_off(1, ks, gm, lane));
        }
        uint32_t b[2][4][2];  // [h][nt][reg]
#pragma unroll
        for (int nt = 0; nt < 4; nt++) {
            int gn = (wid >> 2) * 4 + nt;
            *reinterpret_cast<uint2*>(b[0][nt]) =
                *reinterpret_cast<const uint2*>(sm + SM_BF + bfrag_off(0, ks, gn, lane));
            *reinterpret_cast<uint2*>(b[1][nt]) =
                *reinterpret_cast<const uint2*>(sm + SM_BF + bfrag_off(1, ks, gn, lane));
        }
#pragma unroll
        for (int mt = 0; mt < 2; mt++)
#pragma unroll
            for (int nt = 0; nt < 4; nt++) {
                mma_bf16(acc[mt][nt], a[0][mt], b[0][nt]);  // hi*hi
                mma_bf16(acc[mt][nt], a[0][mt], b[1][nt]);  // hi*lo
                mma_bf16(acc[mt][nt], a[1][mt], b[0][nt]);  // lo*hi
            }
    }

    // ================= epilogue: bias + relu + scattered store =================
    int group = lane >> 2;
    int qc = lane & 3;

    float2 bias[4];
#pragma unroll
    for (int nt = 0; nt < 4; nt++) {
        bias[nt] = *reinterpret_cast<const float2*>(Bv + (size_t)type * D + wn +
                                                    nt * 8 + qc * 2);
    }

#pragma unroll
    for (int mt = 0; mt < 2; mt++) {
#pragma unroll
        for (int half = 0; half < 2; half++) {
            int r = wm + mt * 16 + group + half * 8;
            if (r < m) {
                int e = g_perm[row_start + r];
                float* orow = out + (size_t)e * D;
#pragma unroll
                for (int nt = 0; nt < 4; nt++) {
                    float v0 = fmaxf(acc[mt][nt][half * 2 + 0] + bias[nt].x, 0.0f);
                    float v1 = fmaxf(acc[mt][nt][half * 2 + 1] + bias[nt].y, 0.0f);
                    *reinterpret_cast<float2*>(orow + wn + nt * 8 + qc * 2) =
                        make_float2(v0, v1);
                }
            }
        }
    }
}

// ---------------- launch -------------------------------------------------------
extern "C" void kernel_launch(void* const* d_in, const int* in_sizes, int n_in,
                              void* d_out, int out_size) {
    const float* X = (const float*)d_in[0];
    const void* types = d_in[1];
    const float* W = (const float*)d_in[2];
    const float* Bv = (const float*)d_in[3];
    float* out = (float*)d_out;
    int E = in_sizes[0] / D;

    cudaFuncSetAttribute(k_gemm_mma, cudaFuncAttributeMaxDynamicSharedMemorySize,
                         SMEM_DYN);

    k_init_detect<<<1, 256>>>((const int*)types, E);
    k_hist<<<512, 256>>>(types, E);
    k_scatter<<<(E + 255) / 256, 256>>>(types, E);

    int max_tiles = (E + BM - 1) / BM + N_TYPES;
    k_gemm_mma<<<max_tiles, 256, SMEM_DYN>>>(X, W, Bv, out);
}

// round 6
// speedup vs baseline: 2.1043x; 1.3264x over previous
#include <cuda_runtime.h>
#include <cuda_bf16.h>
#include <cstdint>

#define N_TYPES 8
#define D 64
#define BM 128
#define E_MAX 1048576

// ---------------- scratch ------------------------------------------------------
__device__ int g_counts[N_TYPES];
__device__ int g_cursor[N_TYPES];
__device__ int g_perm[E_MAX];
__device__ int g_is64;
// precomputed B fragments: [type][plane][ks][nt][lane] as uint2
__device__ uint2 g_bfrag[N_TYPES * 2 * 4 * 8 * 32];

// ---------------- helpers ------------------------------------------------------
__device__ __forceinline__ int get_type(const void* p, int i, int is64) {
    if (is64) return (int)((const long long*)p)[i];
    return ((const int*)p)[i];
}
__device__ __forceinline__ uint32_t bf16x2(float x0, float x1) {
    uint32_t r;
    asm("cvt.rn.bf16x2.f32 %0, %1, %2;" : "=r"(r) : "f"(x1), "f"(x0));
    return r;
}
__device__ __forceinline__ float lo_of(uint32_t w) { return __uint_as_float(w << 16); }
__device__ __forceinline__ float hi_of(uint32_t w) {
    return __uint_as_float(w & 0xffff0000u);
}
__device__ __forceinline__ void mma_bf16(float* c, const uint32_t* a,
                                         const uint32_t* b) {
    asm volatile(
        "mma.sync.aligned.m16n8k16.row.col.f32.bf16.bf16.f32 "
        "{%0,%1,%2,%3}, {%4,%5,%6,%7}, {%8,%9}, {%0,%1,%2,%3};"
        : "+f"(c[0]), "+f"(c[1]), "+f"(c[2]), "+f"(c[3])
        : "r"(a[0]), "r"(a[1]), "r"(a[2]), "r"(a[3]), "r"(b[0]), "r"(b[1]));
}
__device__ __forceinline__ void ldmx4(uint32_t* r, uint32_t addr) {
    asm volatile("ldmatrix.sync.aligned.m8n8.x4.shared.b16 {%0,%1,%2,%3}, [%4];"
                 : "=r"(r[0]), "=r"(r[1]), "=r"(r[2]), "=r"(r[3])
                 : "r"(addr));
}
__device__ __forceinline__ uint32_t smem_u32(const void* p) {
    uint32_t a;
    asm("{ .reg .u64 t; cvta.to.shared.u64 t, %1; cvt.u32.u64 %0, t; }"
        : "=r"(a) : "l"(p));
    return a;
}

// ---------------- launch 0: init + dtype detect --------------------------------
__global__ void k_init_detect(const int* __restrict__ t32, int E) {
    __shared__ int any;
    if (threadIdx.x == 0) any = 0;
    if (threadIdx.x < N_TYPES) {
        g_counts[threadIdx.x] = 0;
        g_cursor[threadIdx.x] = 0;
    }
    __syncthreads();
    int stride = E / 2048;
    if (stride < 1) stride = 1;
    for (int i = threadIdx.x; i < 1024; i += blockDim.x) {
        long long idx = 2LL * i * stride + 1;
        if (idx < E && t32[idx] != 0) any = 1;
    }
    __syncthreads();
    if (threadIdx.x == 0) g_is64 = any ? 0 : 1;
}

// ---------------- launch 1: histogram + B-fragment precompute ------------------
__global__ void k_hist(const void* __restrict__ types, const float* __restrict__ W,
                       int E) {
    __shared__ int s[N_TYPES];
    if (threadIdx.x < N_TYPES) s[threadIdx.x] = 0;
    __syncthreads();
    int is64 = g_is64;
    for (int i = blockIdx.x * blockDim.x + threadIdx.x; i < E;
         i += gridDim.x * blockDim.x) {
        atomicAdd(&s[get_type(types, i, is64)], 1);
    }
    __syncthreads();
    if (threadIdx.x < N_TYPES) atomicAdd(&g_counts[threadIdx.x], s[threadIdx.x]);

    // blocks 0..7: build B fragments for type = blockIdx.x
    if (blockIdx.x < N_TYPES) {
        int t = blockIdx.x;
        const float* Wt = W + (size_t)t * D * D;
        for (int it = threadIdx.x; it < 4 * 8 * 32; it += blockDim.x) {
            int ks = it >> 8;
            int nt = (it >> 5) & 7;
            int lane = it & 31;
            int col = nt * 8 + (lane >> 2);
            int k0 = ks * 16 + 2 * (lane & 3);
            float w00 = Wt[k0 * D + col];
            float w01 = Wt[(k0 + 1) * D + col];
            float w10 = Wt[(k0 + 8) * D + col];
            float w11 = Wt[(k0 + 9) * D + col];
            uint32_t b0h = bf16x2(w00, w01);
            uint32_t b1h = bf16x2(w10, w11);
            uint32_t b0l = bf16x2(w00 - lo_of(b0h), w01 - hi_of(b0h));
            uint32_t b1l = bf16x2(w10 - lo_of(b1h), w11 - hi_of(b1h));
            // layout [type][plane][ks][nt][lane]
            g_bfrag[(((t * 2 + 0) * 4 + ks) * 8 + nt) * 32 + lane] =
                make_uint2(b0h, b1h);
            g_bfrag[(((t * 2 + 1) * 4 + ks) * 8 + nt) * 32 + lane] =
                make_uint2(b0l, b1l);
        }
    }
}

// ---------------- launch 2: scatter --------------------------------------------
__global__ void k_scatter(const void* __restrict__ types, int E) {
    __shared__ int s_cnt[N_TYPES], s_base[N_TYPES];
    if (threadIdx.x < N_TYPES) s_cnt[threadIdx.x] = 0;
    __syncthreads();
    int e = blockIdx.x * blockDim.x + threadIdx.x;
    int t = 0, local = 0;
    int valid = (e < E);
    if (valid) {
        t = get_type(types, e, g_is64);
        local = atomicAdd(&s_cnt[t], 1);
    }
    __syncthreads();
    if (threadIdx.x < N_TYPES) {
        int off = 0;
        for (int u = 0; u < N_TYPES; u++) {
            if (u == threadIdx.x) break;
            off += g_counts[u];
        }
        s_base[threadIdx.x] = off + atomicAdd(&g_cursor[threadIdx.x], s_cnt[threadIdx.x]);
    }
    __syncthreads();
    if (valid) g_perm[s_base[t] + local] = e;
}

// ---------------- launch 3: ldmatrix + mma grouped GEMM ------------------------
// A: [2 planes][128 rows][128B] xor-swizzled bf16, STS.128-filled, ldmatrix-read.
// B: 16KB precomputed fragment image for this block's type, LDS.64-read.
__global__ void __launch_bounds__(256) k_gemm_mma(const float* __restrict__ X,
                                                  const float* __restrict__ Bv,
                                                  float* __restrict__ out) {
    __shared__ char smA[2 * 128 * 128];     // 32KB
    __shared__ uint2 smB[2 * 4 * 8 * 32];   // 16KB

    // ---- map blockIdx.x -> (type, tile) ----
    int tile = blockIdx.x;
    int type = -1, row_start = 0, m = 0;
    {
        int acc_tiles = 0, off = 0;
#pragma unroll
        for (int t = 0; t < N_TYPES; t++) {
            int c = g_counts[t];
            int nt = (c + BM - 1) / BM;
            if (type < 0 && tile < acc_tiles + nt) {
                type = t;
                int lt = tile - acc_tiles;
                row_start = off + lt * BM;
                m = c - lt * BM;
                if (m > BM) m = BM;
            }
            acc_tiles += nt;
            off += c;
        }
    }
    if (type < 0) return;

    int tid = threadIdx.x;
    uint32_t sA = smem_u32(smA);

    // ---- B fragment copy: 16KB, 4x uint4 per thread ----
    {
        const uint4* src =
            reinterpret_cast<const uint4*>(g_bfrag + (size_t)type * 2048);
        uint4* dst = reinterpret_cast<uint4*>(smB);
#pragma unroll
        for (int i = 0; i < 4; i++) dst[tid + i * 256] = src[tid + i * 256];
    }

    // ---- A fill: thread = (row, k-half); split bf16 planes; STS.128 swizzled ----
    {
        int r = tid & 127;
        int h = tid >> 7;
        int rr = (r < m) ? r : (m - 1);
        int e = g_perm[row_start + rr];
        const float4* Xe = reinterpret_cast<const float4*>(X + (size_t)e * D) + h * 8;
        uint32_t hi[16], lo[16];
#pragma unroll
        for (int q = 0; q < 8; q++) {
            float4 v = Xe[q];
            uint32_t w0 = bf16x2(v.x, v.y);
            uint32_t w1 = bf16x2(v.z, v.w);
            hi[2 * q] = w0;
            hi[2 * q + 1] = w1;
            lo[2 * q] = bf16x2(v.x - lo_of(w0), v.y - hi_of(w0));
            lo[2 * q + 1] = bf16x2(v.z - lo_of(w1), v.w - hi_of(w1));
        }
        uint32_t rowb = (uint32_t)r * 128;
#pragma unroll
        for (int cc = 0; cc < 4; cc++) {
            int c = h * 4 + cc;
            uint32_t off = rowb + (uint32_t)((c ^ (r & 7)) << 4);
            *reinterpret_cast<uint4*>(smA + off) =
                make_uint4(hi[4 * cc], hi[4 * cc + 1], hi[4 * cc + 2], hi[4 * cc + 3]);
            *reinterpret_cast<uint4*>(smA + 16384 + off) =
                make_uint4(lo[4 * cc], lo[4 * cc + 1], lo[4 * cc + 2], lo[4 * cc + 3]);
        }
    }
    __syncthreads();

    // ---- main loop ----
    int wid = tid >> 5;
    int lane = tid & 31;
    int wm = (wid & 3) * 32;
    int wnq = (wid >> 2);  // 0/1 -> n offset wnq*32

    float acc[2][4][4];
#pragma unroll
    for (int mt = 0; mt < 2; mt++)
#pragma unroll
        for (int nt = 0; nt < 4; nt++)
#pragma unroll
            for (int i = 0; i < 4; i++) acc[mt][nt][i] = 0.0f;

    // per-warp ldmatrix address components
    int lrow[2];
#pragma unroll
    for (int mt = 0; mt < 2; mt++) lrow[mt] = wm + mt * 16 + (lane & 15);
    int cadd = lane >> 4;  // 0/1

#pragma unroll
    for (int ks = 0; ks < 4; ks++) {
        uint32_t a[2][2][4];  // [plane][mt][reg]
#pragma unroll
        for (int mt = 0; mt < 2; mt++) {
            int c = ks * 2 + cadd;
            uint32_t off =
                (uint32_t)lrow[mt] * 128 + (uint32_t)((c ^ (lrow[mt] & 7)) << 4);
            ldmx4(a[0][mt], sA + off);
            ldmx4(a[1][mt], sA + 16384 + off);
        }
        uint32_t b[2][4][2];  // [plane][nt][reg]
#pragma unroll
        for (int p = 0; p < 2; p++)
#pragma unroll
            for (int nt = 0; nt < 4; nt++) {
                uint2 v = smB[((p * 4 + ks) * 8 + wnq * 4 + nt) * 32 + lane];
                b[p][nt][0] = v.x;
                b[p][nt][1] = v.y;
            }
#pragma unroll
        for (int mt = 0; mt < 2; mt++)
#pragma unroll
            for (int nt = 0; nt < 4; nt++) {
                mma_bf16(acc[mt][nt], a[0][mt], b[0][nt]);  // hi*hi
                mma_bf16(acc[mt][nt], a[0][mt], b[1][nt]);  // hi*lo
                mma_bf16(acc[mt][nt], a[1][mt], b[0][nt]);  // lo*hi
            }
    }

    // ---- epilogue: bias + relu + scattered store ----
    int wn = wnq * 32;
    int group = lane >> 2;
    int qc = lane & 3;

    float2 bias[4];
#pragma unroll
    for (int nt = 0; nt < 4; nt++) {
        bias[nt] = *reinterpret_cast<const float2*>(Bv + (size_t)type * D + wn +
                                                    nt * 8 + qc * 2);
    }

#pragma unroll
    for (int mt = 0; mt < 2; mt++) {
#pragma unroll
        for (int half = 0; half < 2; half++) {
            int r = wm + mt * 16 + group + half * 8;
            if (r < m) {
                int e = g_perm[row_start + r];
                float* orow = out + (size_t)e * D;
#pragma unroll
                for (int nt = 0; nt < 4; nt++) {
                    float v0 = fmaxf(acc[mt][nt][half * 2 + 0] + bias[nt].x, 0.0f);
                    float v1 = fmaxf(acc[mt][nt][half * 2 + 1] + bias[nt].y, 0.0f);
                    *reinterpret_cast<float2*>(orow + wn + nt * 8 + qc * 2) =
                        make_float2(v0, v1);
                }
            }
        }
    }
}

// ---------------- launch -------------------------------------------------------
extern "C" void kernel_launch(void* const* d_in, const int* in_sizes, int n_in,
                              void* d_out, int out_size) {
    const float* X = (const float*)d_in[0];
    const void* types = d_in[1];
    const float* W = (const float*)d_in[2];
    const float* Bv = (const float*)d_in[3];
    float* out = (float*)d_out;
    int E = in_sizes[0] / D;

    k_init_detect<<<1, 256>>>((const int*)types, E);
    k_hist<<<512, 256>>>(types, W, E);
    k_scatter<<<(E + 255) / 256, 256>>>(types, E);

    int max_tiles = (E + BM - 1) / BM + N_TYPES;
    k_gemm_mma<<<max_tiles, 256>>>(X, Bv, out);
}